// round 4
// baseline (speedup 1.0000x reference)
#include <cuda_runtime.h>
#include <math.h>

#define N_NODES 100000
#define N_EDGES 1600000
#define IN_DIM 128
#define HID 64
#define NTILES ((N_NODES + 255) / 256)   // 391

// ---------------- scratch (__device__ globals; referenced from DEVICE code only) ----------------
__device__ int d_is64;                         // 1 if edge_index delivered as int64
__device__ __align__(16) int d_src[N_EDGES];   // canonical int32 src
__device__ __align__(16) int d_dst[N_EDGES];   // canonical int32 dst
__device__ __align__(16) int d_cnt[N_NODES];
__device__ __align__(16) int d_rowptr[N_NODES + 1];
__device__ __align__(16) int d_bsum[512];
__device__ __align__(16) int d_boff[512];
__device__ __align__(16) int d_eidx[N_EDGES];
__device__ __align__(16) float d_dinv[N_NODES];
__device__ __align__(16) float d_g1[(size_t)N_NODES * HID];   // (x@W1)*dinv
__device__ __align__(16) float d_h1[(size_t)N_NODES * HID];   // relu(dinv*agg + b1)
__device__ __align__(16) float d_g2[(size_t)N_NODES * HID];   // (h1@W2)*dinv
__device__ __align__(16) float d_emb[(size_t)N_NODES * HID];  // dinv*agg + b2

// ---------------- dtype detection + canonicalization ----------------
// If edge_index is int64 (values < 2^31), every odd 32-bit word of the buffer is 0.
// If it is int32, odd words are random node ids (~all nonzero). Sample 2048 words.
__global__ void detect_kernel(const int* __restrict__ ei32) {
    __shared__ int any_nonzero;
    if (threadIdx.x == 0) any_nonzero = 0;
    __syncthreads();
    int local = 0;
    for (int i = threadIdx.x; i < 2048; i += blockDim.x)
        local |= ei32[2 * i + 1];
    if (local) atomicOr(&any_nonzero, 1);
    __syncthreads();
    if (threadIdx.x == 0) d_is64 = (any_nonzero == 0) ? 1 : 0;
}

__global__ void convert_kernel(const int* __restrict__ ei32) {
    int e = blockIdx.x * blockDim.x + threadIdx.x;
    if (e >= N_EDGES) return;
    int s, d;
    if (d_is64) {               // little-endian int64: low word holds the value
        s = ei32[2 * e];
        d = ei32[2 * (N_EDGES + e)];
    } else {
        s = ei32[e];
        d = ei32[N_EDGES + e];
    }
    // clamp: no input can ever produce a wild address downstream
    s = min(max(s, 0), N_NODES - 1);
    d = min(max(d, 0), N_NODES - 1);
    d_src[e] = s;
    d_dst[e] = d;
}

// ---------------- CSR build ----------------
__global__ void zero_cnt_kernel() {
    int i = blockIdx.x * blockDim.x + threadIdx.x;
    if (i < N_NODES) d_cnt[i] = 0;
}

__global__ void hist_kernel() {
    int e = blockIdx.x * blockDim.x + threadIdx.x;
    if (e < N_EDGES) atomicAdd(&d_cnt[d_dst[e]], 1);
}

__global__ void dinv_kernel() {
    int i = blockIdx.x * blockDim.x + threadIdx.x;
    if (i < N_NODES) d_dinv[i] = rsqrtf((float)d_cnt[i] + 1.0f);  // +1 self-loop
}

// per-256-tile inclusive scan; tile totals to d_bsum
__global__ void scanA_kernel() {
    __shared__ int s[256];
    int t = threadIdx.x;
    int i = blockIdx.x * 256 + t;
    int v = (i < N_NODES) ? d_cnt[i] : 0;
    s[t] = v;
    __syncthreads();
#pragma unroll
    for (int off = 1; off < 256; off <<= 1) {
        int a = (t >= off) ? s[t - off] : 0;
        __syncthreads();
        s[t] += a;
        __syncthreads();
    }
    if (i < N_NODES) d_rowptr[i + 1] = s[t];
    if (t == 255) d_bsum[blockIdx.x] = s[255];
}

// single-block exclusive scan of tile totals
__global__ void scanB_kernel() {
    __shared__ int s[512];
    int t = threadIdx.x;
    int v = (t < NTILES) ? d_bsum[t] : 0;
    s[t] = v;
    __syncthreads();
#pragma unroll
    for (int off = 1; off < 512; off <<= 1) {
        int a = (t >= off) ? s[t - off] : 0;
        __syncthreads();
        s[t] += a;
        __syncthreads();
    }
    d_boff[t] = s[t] - v;  // exclusive
}

__global__ void scanC_kernel() {
    int i = blockIdx.x * 256 + threadIdx.x;
    if (i < N_NODES) d_rowptr[i + 1] += d_boff[blockIdx.x];
    if (i == 0) d_rowptr[0] = 0;
}

__global__ void fill_kernel() {
    int e = blockIdx.x * blockDim.x + threadIdx.x;
    if (e >= N_EDGES) return;
    int d = d_dst[e];
    int pos = d_rowptr[d] + atomicAdd(&d_cnt[d], 1);
    d_eidx[pos] = d_src[e];
}

// ---------------- GEMM: out = (in @ W) * dinv   (64x64 tile, 256 thr, 4x4 micro) ----------------
// LAYER 0: in = x (param), out = d_g1.  LAYER 1: in = d_h1, out = d_g2.
template <int KDIM, int LAYER>
__global__ __launch_bounds__(256) void gemm_kernel(const float* __restrict__ xin,
                                                   const float* __restrict__ W) {
    const float* in = (LAYER == 0) ? xin : d_h1;
    float* out = (LAYER == 0) ? d_g1 : d_g2;

    __shared__ float sX[64 * 64];
    __shared__ float sW[64 * 64];
    int tid = threadIdx.x;
    int r0 = blockIdx.x * 64;
    int jg = tid & 15;   // col group (4 cols)
    int rg = tid >> 4;   // row group; rows rg + {0,16,32,48}

    float acc[4][4];
#pragma unroll
    for (int a = 0; a < 4; a++)
#pragma unroll
        for (int b = 0; b < 4; b++) acc[a][b] = 0.0f;

#pragma unroll
    for (int kp = 0; kp < KDIM / 64; kp++) {
        for (int i = tid; i < 4096; i += 256) sW[i] = W[kp * 4096 + i];
#pragma unroll
        for (int it = 0; it < 4; it++) {
            int r = rg + 16 * it;
            int row = r0 + r;
            float4 v = make_float4(0.f, 0.f, 0.f, 0.f);
            if (row < N_NODES)
                v = *(const float4*)(in + (size_t)row * KDIM + kp * 64 + jg * 4);
            *(float4*)(sX + r * 64 + jg * 4) = v;
        }
        __syncthreads();
#pragma unroll 8
        for (int k = 0; k < 64; k++) {
            float4 w4 = *(const float4*)(sW + k * 64 + jg * 4);
            float x0 = sX[(rg + 0) * 64 + k];
            float x1 = sX[(rg + 16) * 64 + k];
            float x2 = sX[(rg + 32) * 64 + k];
            float x3 = sX[(rg + 48) * 64 + k];
            acc[0][0] = fmaf(x0, w4.x, acc[0][0]); acc[0][1] = fmaf(x0, w4.y, acc[0][1]);
            acc[0][2] = fmaf(x0, w4.z, acc[0][2]); acc[0][3] = fmaf(x0, w4.w, acc[0][3]);
            acc[1][0] = fmaf(x1, w4.x, acc[1][0]); acc[1][1] = fmaf(x1, w4.y, acc[1][1]);
            acc[1][2] = fmaf(x1, w4.z, acc[1][2]); acc[1][3] = fmaf(x1, w4.w, acc[1][3]);
            acc[2][0] = fmaf(x2, w4.x, acc[2][0]); acc[2][1] = fmaf(x2, w4.y, acc[2][1]);
            acc[2][2] = fmaf(x2, w4.z, acc[2][2]); acc[2][3] = fmaf(x2, w4.w, acc[2][3]);
            acc[3][0] = fmaf(x3, w4.x, acc[3][0]); acc[3][1] = fmaf(x3, w4.y, acc[3][1]);
            acc[3][2] = fmaf(x3, w4.z, acc[3][2]); acc[3][3] = fmaf(x3, w4.w, acc[3][3]);
        }
        __syncthreads();
    }
#pragma unroll
    for (int ri = 0; ri < 4; ri++) {
        int row = r0 + rg + 16 * ri;
        if (row < N_NODES) {
            float dv = d_dinv[row];
            float4 o = make_float4(acc[ri][0] * dv, acc[ri][1] * dv,
                                   acc[ri][2] * dv, acc[ri][3] * dv);
            *(float4*)(out + (size_t)row * HID + jg * 4) = o;
        }
    }
}

// ---------------- gather-aggregate: out[n] = post(dinv[n]*(g[n] + sum g[src]) + bias) ----------
// LAYER 0: g=d_g1, out=d_h1, relu.  LAYER 1: g=d_g2, out=d_emb, no relu.
// 16 threads per node, each owns one float4 lane; 4-edge unroll for MLP.
template <int LAYER>
__global__ __launch_bounds__(256) void gather_kernel(const float* __restrict__ bias) {
    const float* g = (LAYER == 0) ? d_g1 : d_g2;
    float* out = (LAYER == 0) ? d_h1 : d_emb;

    int t = threadIdx.x;
    int node = blockIdx.x * 16 + (t >> 4);
    if (node >= N_NODES) return;
    int lane = t & 15;

    int base = d_rowptr[node];
    int end  = d_rowptr[node + 1];

    float4 a0 = *(const float4*)(g + (size_t)node * HID + lane * 4);  // self-loop
    float4 a1 = make_float4(0.f, 0.f, 0.f, 0.f);
    float4 a2 = make_float4(0.f, 0.f, 0.f, 0.f);
    float4 a3 = make_float4(0.f, 0.f, 0.f, 0.f);

    int i = base;
    for (; i + 4 <= end; i += 4) {
        int s0 = d_eidx[i + 0];
        int s1 = d_eidx[i + 1];
        int s2 = d_eidx[i + 2];
        int s3 = d_eidx[i + 3];
        float4 v0 = *(const float4*)(g + (size_t)s0 * HID + lane * 4);
        float4 v1 = *(const float4*)(g + (size_t)s1 * HID + lane * 4);
        float4 v2 = *(const float4*)(g + (size_t)s2 * HID + lane * 4);
        float4 v3 = *(const float4*)(g + (size_t)s3 * HID + lane * 4);
        a0.x += v0.x; a0.y += v0.y; a0.z += v0.z; a0.w += v0.w;
        a1.x += v1.x; a1.y += v1.y; a1.z += v1.z; a1.w += v1.w;
        a2.x += v2.x; a2.y += v2.y; a2.z += v2.z; a2.w += v2.w;
        a3.x += v3.x; a3.y += v3.y; a3.z += v3.z; a3.w += v3.w;
    }
    for (; i < end; i++) {
        int s = d_eidx[i];
        float4 v = *(const float4*)(g + (size_t)s * HID + lane * 4);
        a0.x += v.x; a0.y += v.y; a0.z += v.z; a0.w += v.w;
    }
    float4 sum = make_float4(a0.x + a1.x + a2.x + a3.x,
                             a0.y + a1.y + a2.y + a3.y,
                             a0.z + a1.z + a2.z + a3.z,
                             a0.w + a1.w + a2.w + a3.w);
    float dv = d_dinv[node];
    float4 bb = *(const float4*)(bias + lane * 4);
    float4 o;
    o.x = fmaf(dv, sum.x, bb.x);
    o.y = fmaf(dv, sum.y, bb.y);
    o.z = fmaf(dv, sum.z, bb.z);
    o.w = fmaf(dv, sum.w, bb.w);
    if (LAYER == 0) {
        o.x = fmaxf(o.x, 0.f); o.y = fmaxf(o.y, 0.f);
        o.z = fmaxf(o.z, 0.f); o.w = fmaxf(o.w, 0.f);
    }
    *(float4*)(out + (size_t)node * HID + lane * 4) = o;
}

// ---------------- final: logits = emb@Wl + bl; log_softmax. one warp/node ----------------
__global__ __launch_bounds__(256) void final_kernel(const float* __restrict__ Wl,
                                                    const float* __restrict__ bl,
                                                    float* __restrict__ out) {
    __shared__ float sWl[64 * 40];
    __shared__ float sbl[40];
    __shared__ float semb[8][64];
    int tid = threadIdx.x;
    for (int i = tid; i < 64 * 40; i += 256) sWl[i] = Wl[i];
    if (tid < 40) sbl[tid] = bl[tid];
    __syncthreads();

    int w = tid >> 5, lane = tid & 31;
    int n = blockIdx.x * 8 + w;
    if (n >= N_NODES) return;

    float e0 = d_emb[(size_t)n * HID + lane];
    float e1 = d_emb[(size_t)n * HID + 32 + lane];
    semb[w][lane] = e0;
    semb[w][32 + lane] = e1;
    __syncwarp();

    float v0 = sbl[lane];
    float v1 = (lane < 8) ? sbl[32 + lane] : -INFINITY;
#pragma unroll 8
    for (int k = 0; k < 64; k++) {
        float ev = semb[w][k];
        v0 = fmaf(ev, sWl[k * 40 + lane], v0);
        if (lane < 8) v1 = fmaf(ev, sWl[k * 40 + 32 + lane], v1);
    }
    float m = fmaxf(v0, v1);
#pragma unroll
    for (int o = 16; o; o >>= 1) m = fmaxf(m, __shfl_xor_sync(0xffffffffu, m, o));
    float s = expf(v0 - m) + ((lane < 8) ? expf(v1 - m) : 0.0f);
#pragma unroll
    for (int o = 16; o; o >>= 1) s += __shfl_xor_sync(0xffffffffu, s, o);
    float lse = m + logf(s);

    out[(size_t)n * 40 + lane] = v0 - lse;
    if (lane < 8) out[(size_t)n * 40 + 32 + lane] = v1 - lse;
}

extern "C" void kernel_launch(void* const* d_in, const int* in_sizes, int n_in,
                              void* d_out, int out_size) {
    const float* x = (const float*)d_in[0];
    const int* ei32 = (const int*)d_in[1];   // int32 OR int64 — detected on device
    const float* W1 = (const float*)d_in[2];
    const float* b1 = (const float*)d_in[3];
    const float* W2 = (const float*)d_in[4];
    const float* b2 = (const float*)d_in[5];
    const float* Wl = (const float*)d_in[6];
    const float* bl = (const float*)d_in[7];
    float* out = (float*)d_out;

    // canonicalize edge index dtype, then CSR build + norms
    detect_kernel<<<1, 256>>>(ei32);
    convert_kernel<<<(N_EDGES + 255) / 256, 256>>>(ei32);
    zero_cnt_kernel<<<NTILES, 256>>>();
    hist_kernel<<<(N_EDGES + 255) / 256, 256>>>();
    dinv_kernel<<<NTILES, 256>>>();
    scanA_kernel<<<NTILES, 256>>>();
    scanB_kernel<<<1, 512>>>();
    scanC_kernel<<<NTILES, 256>>>();
    zero_cnt_kernel<<<NTILES, 256>>>();
    fill_kernel<<<(N_EDGES + 255) / 256, 256>>>();

    // layer 1
    gemm_kernel<IN_DIM, 0><<<(N_NODES + 63) / 64, 256>>>(x, W1);
    gather_kernel<0><<<(N_NODES + 15) / 16, 256>>>(b1);

    // layer 2
    gemm_kernel<HID, 1><<<(N_NODES + 63) / 64, 256>>>(nullptr, W2);
    gather_kernel<1><<<(N_NODES + 15) / 16, 256>>>(b2);

    // classifier + log_softmax
    final_kernel<<<(N_NODES + 7) / 8, 256>>>(Wl, bl, out);
}